// round 13
// baseline (speedup 1.0000x reference)
#include <cuda_runtime.h>

// ---------------------------------------------------------------------------
// Batch-independent factorization of the collapsed reference:
//   out[b,s,h*64+e] = RV[b,h,e] * beta[b,s,h] * (S_mas[b,s] != 0)
//   beta[b,s,h] = dot(S[b,s,h*64:], W[b,h,:]) + c[b,h]
//   W[b,h,d]  = b0[d]   + sum_d' At[d',d] * r[b,h,d']     At = WQ_w^T WK_w
//   c[b,h]    = c0      + sum_d' u[d']    * r[b,h,d']     u  = WK_w^T WQ_b
//   RV[b,h,e] = WV_b[e] + sum_d  WVt[d,e] * r[b,h,d]      WVt = WV_w^T
// Node 1: weights_kernel (71 blocks, e-split chains -> latency-minimal).
// Node 2: fused kernel — cheap 2-pass coalesced prologue (no forced reg
// bound -> no spills) + the proven HBM-bound streaming loop.
// ---------------------------------------------------------------------------

__device__ float g_At [64 * 64];   // [d'][d], d fast
__device__ float g_WVt[64 * 64];   // [d][e],  e fast
__device__ float g_u  [64];
__device__ float g_b0 [64];
__device__ float g_c0;

// ---------------------------------------------------------------------------
// weights_kernel: grid 71, block 256.
//  blocks 0..63 : At row d' = g. thread (d = t&63, part = t>>6): 16-e
//                 partial (MLP=16, coalesced over d), 4-way smem reduce.
//  blocks 64..67: WVt transpose quarter (coalesced writes).
//  block  68    : u  (e-split x4 + smem reduce).
//  block  69    : b0 (e-split x4 + smem reduce).
//  block  70    : c0 (thread 0, 4 independent partials).
// ---------------------------------------------------------------------------
__global__ __launch_bounds__(256) void weights_kernel(
    const float* __restrict__ WQ_w, const float* __restrict__ WQ_b,
    const float* __restrict__ WK_w, const float* __restrict__ WK_b,
    const float* __restrict__ WV_w) {
    const int g = blockIdx.x;
    const int t = threadIdx.x;
    __shared__ float red[256];

    if (g < 64) {
        const int d    = t & 63;
        const int part = t >> 6;           // 4 parts x 16 e's
        float acc = 0.f;
#pragma unroll 16
        for (int i = 0; i < 16; i++) {
            const int e = part * 16 + i;
            acc = fmaf(WQ_w[e * 64 + d], WK_w[e * 64 + g], acc);
        }
        red[t] = acc;
        __syncthreads();
        if (part == 0)
            g_At[g * 64 + d] = acc + red[d + 64] + red[d + 128] + red[d + 192];
    } else if (g < 68) {
        const int k = g - 64;              // 0..3
#pragma unroll
        for (int i = 0; i < 4; i++) {
            const int idx = k * 1024 + i * 256 + t;
            const int d = idx >> 6, e = idx & 63;
            g_WVt[d * 64 + e] = WV_w[e * 64 + d];   // write coalesced
        }
    } else if (g == 68) {
        const int dp   = t & 63;
        const int part = t >> 6;
        float acc = 0.f;
#pragma unroll 16
        for (int i = 0; i < 16; i++) {
            const int e = part * 16 + i;
            acc = fmaf(WQ_b[e], WK_w[e * 64 + dp], acc);
        }
        red[t] = acc;
        __syncthreads();
        if (part == 0)
            g_u[dp] = acc + red[dp + 64] + red[dp + 128] + red[dp + 192];
    } else if (g == 69) {
        const int d    = t & 63;
        const int part = t >> 6;
        float acc = 0.f;
#pragma unroll 16
        for (int i = 0; i < 16; i++) {
            const int e = part * 16 + i;
            acc = fmaf(WQ_w[e * 64 + d], WK_b[e], acc);
        }
        red[t] = acc;
        __syncthreads();
        if (part == 0)
            g_b0[d] = acc + red[d + 64] + red[d + 128] + red[d + 192];
    } else {
        if (t == 0) {
            float a0 = 0.f, a1 = 0.f, a2 = 0.f, a3 = 0.f;
#pragma unroll 4
            for (int e = 0; e < 64; e += 4) {
                a0 = fmaf(WQ_b[e + 0], WK_b[e + 0], a0);
                a1 = fmaf(WQ_b[e + 1], WK_b[e + 1], a1);
                a2 = fmaf(WQ_b[e + 2], WK_b[e + 2], a2);
                a3 = fmaf(WQ_b[e + 3], WK_b[e + 3], a3);
            }
            g_c0 = (a0 + a1) + (a2 + a3);
        }
    }
}

// ---------------------------------------------------------------------------
// Fused kernel. Prologue roles: role = t&127 -> (q = role&15 d/e-quad,
// hp = role>>4 -> heads {hp, hp+8}); half = t>>7 splits d' in [0,32)/[32,64).
// TWO PASSES (W+c, then RV) keep <=8 live accumulators; NO min-blocks bound
// so ptxas never spills (R10 failure mode). All At/WVt loads are 256B
// fast-axis float4; r is broadcast LDS. Reduce + handoff via smem.
// ---------------------------------------------------------------------------
template <int ROWS_PER_BLOCK, int UNROLL>
__global__ __launch_bounds__(256) void fused_kernel(
    const float* __restrict__ S,
    const float* __restrict__ R,
    const int*   __restrict__ S_mas,
    const float* __restrict__ WV_b,
    float*       __restrict__ out,
    int seq) {
    const int b = blockIdx.x;
    const int t = threadIdx.x;

    __shared__ float  r_s [1024];   // 4 KB
    __shared__ float4 w_s [256];    // 4 KB  (slot = h*16+q = tid)
    __shared__ float4 rv_s[256];    // 4 KB
    __shared__ float  c_s [16];

#pragma unroll
    for (int i = 0; i < 4; i++)
        r_s[i * 256 + t] = R[b * 1024 + i * 256 + t];
    __syncthreads();

    {
        const int role = t & 127;
        const int q    = role & 15;
        const int hp   = role >> 4;        // 0..7
        const int half = t >> 7;           // 0 or 1
        const int h0 = hp, h1 = hp + 8;
        const float* r0p = r_s + h0 * 64 + half * 32;
        const float* r1p = r_s + h1 * 64 + half * 32;
        const int    dbase = half * 32;

        // ---- Pass 1: W quads + c ----
        {
            float4 w0 = {0, 0, 0, 0}, w1 = {0, 0, 0, 0};
            float  ca = 0.f, cb = 0.f;
            const float4* At4 = reinterpret_cast<const float4*>(g_At);
#pragma unroll 4
            for (int j = 0; j < 32; j++) {
                const int   d   = dbase + j;
                const float rr0 = r0p[j];
                const float rr1 = r1p[j];
                const float4 a4 = At4[d * 16 + q];     // coalesced 256B
                w0.x = fmaf(a4.x, rr0, w0.x); w0.y = fmaf(a4.y, rr0, w0.y);
                w0.z = fmaf(a4.z, rr0, w0.z); w0.w = fmaf(a4.w, rr0, w0.w);
                w1.x = fmaf(a4.x, rr1, w1.x); w1.y = fmaf(a4.y, rr1, w1.y);
                w1.z = fmaf(a4.z, rr1, w1.z); w1.w = fmaf(a4.w, rr1, w1.w);
                const float uu = g_u[d];               // uniform
                ca = fmaf(uu, rr0, ca);
                cb = fmaf(uu, rr1, cb);
            }
            if (half == 1) {
                w_s[h0 * 16 + q] = w0;  w_s[h1 * 16 + q] = w1;
                if (q == 0) { c_s[h0] = ca; c_s[h1] = cb; }
            }
            __syncthreads();
            if (half == 0) {
                const float4 b0q = reinterpret_cast<const float4*>(g_b0)[q];
                float4 p;
                p = w_s[h0 * 16 + q];
                w_s[h0 * 16 + q] = make_float4(
                    w0.x + p.x + b0q.x, w0.y + p.y + b0q.y,
                    w0.z + p.z + b0q.z, w0.w + p.w + b0q.w);
                p = w_s[h1 * 16 + q];
                w_s[h1 * 16 + q] = make_float4(
                    w1.x + p.x + b0q.x, w1.y + p.y + b0q.y,
                    w1.z + p.z + b0q.z, w1.w + p.w + b0q.w);
                if (q == 0) {
                    c_s[h0] = ca + c_s[h0] + g_c0;
                    c_s[h1] = cb + c_s[h1] + g_c0;
                }
            }
        }

        // ---- Pass 2: RV quads ----
        {
            float4 v0 = {0, 0, 0, 0}, v1 = {0, 0, 0, 0};
            const float4* Vt4 = reinterpret_cast<const float4*>(g_WVt);
#pragma unroll 4
            for (int j = 0; j < 32; j++) {
                const int   d   = dbase + j;
                const float rr0 = r0p[j];
                const float rr1 = r1p[j];
                const float4 v4 = Vt4[d * 16 + q];     // coalesced 256B
                v0.x = fmaf(v4.x, rr0, v0.x); v0.y = fmaf(v4.y, rr0, v0.y);
                v0.z = fmaf(v4.z, rr0, v0.z); v0.w = fmaf(v4.w, rr0, v0.w);
                v1.x = fmaf(v4.x, rr1, v1.x); v1.y = fmaf(v4.y, rr1, v1.y);
                v1.z = fmaf(v4.z, rr1, v1.z); v1.w = fmaf(v4.w, rr1, v1.w);
            }
            if (half == 1) {
                rv_s[h0 * 16 + q] = v0;  rv_s[h1 * 16 + q] = v1;
            }
            __syncthreads();
            if (half == 0) {
                const float4 vbq = reinterpret_cast<const float4*>(WV_b)[q];
                float4 p;
                p = rv_s[h0 * 16 + q];
                rv_s[h0 * 16 + q] = make_float4(
                    v0.x + p.x + vbq.x, v0.y + p.y + vbq.y,
                    v0.z + p.z + vbq.z, v0.w + p.w + vbq.w);
                p = rv_s[h1 * 16 + q];
                rv_s[h1 * 16 + q] = make_float4(
                    v1.x + p.x + vbq.x, v1.y + p.y + vbq.y,
                    v1.z + p.z + vbq.z, v1.w + p.w + vbq.w);
            }
        }
        __syncthreads();
    }

    // ---- Per-thread stream constants: slot == tid by construction ----
    const float4 w4  = w_s[t];
    const float4 rv4 = rv_s[t];
    const float  c   = c_s[t >> 4];

    // ---- Streaming pass (proven ~80us / 77% DRAM configuration) ----
    const int row0 = blockIdx.y * ROWS_PER_BLOCK;
    const float4* Sp = reinterpret_cast<const float4*>(S) + (size_t)b * seq * 256;
    float4*       Op = reinterpret_cast<float4*>(out)     + (size_t)b * seq * 256;
    const int*    mp = S_mas + (size_t)b * seq;

    const int row_end = (row0 + ROWS_PER_BLOCK < seq) ? row0 + ROWS_PER_BLOCK : seq;

    int r = row0;
    for (; r + UNROLL <= row_end; r += UNROLL) {
        float4 s[UNROLL];
        int    m[UNROLL];
#pragma unroll
        for (int u2 = 0; u2 < UNROLL; u2++) {
            s[u2] = Sp[(size_t)(r + u2) * 256 + t];
            m[u2] = mp[r + u2];
        }
#pragma unroll
        for (int u2 = 0; u2 < UNROLL; u2++) {
            float p = s[u2].x * w4.x + s[u2].y * w4.y + s[u2].z * w4.z + s[u2].w * w4.w;
            p += __shfl_xor_sync(0xffffffffu, p, 8, 16);
            p += __shfl_xor_sync(0xffffffffu, p, 4, 16);
            p += __shfl_xor_sync(0xffffffffu, p, 2, 16);
            p += __shfl_xor_sync(0xffffffffu, p, 1, 16);
            const float beta = (p + c) * (m[u2] != 0 ? 1.0f : 0.0f);
            float4 o;
            o.x = rv4.x * beta;
            o.y = rv4.y * beta;
            o.z = rv4.z * beta;
            o.w = rv4.w * beta;
            Op[(size_t)(r + u2) * 256 + t] = o;
        }
    }
    for (; r < row_end; r++) {
        float4 s = Sp[(size_t)r * 256 + t];
        int    m = mp[r];
        float p = s.x * w4.x + s.y * w4.y + s.z * w4.z + s.w * w4.w;
        p += __shfl_xor_sync(0xffffffffu, p, 8, 16);
        p += __shfl_xor_sync(0xffffffffu, p, 4, 16);
        p += __shfl_xor_sync(0xffffffffu, p, 2, 16);
        p += __shfl_xor_sync(0xffffffffu, p, 1, 16);
        const float beta = (p + c) * (m != 0 ? 1.0f : 0.0f);
        float4 o;
        o.x = rv4.x * beta;
        o.y = rv4.y * beta;
        o.z = rv4.z * beta;
        o.w = rv4.w * beta;
        Op[(size_t)r * 256 + t] = o;
    }
}

// ---------------------------------------------------------------------------
// Launch. Inputs (metadata order):
//   0 S (dps,seq,1024) f32   1 R (dps,1,1024) f32
//   2 S_mas (dps,seq,1) i32  3 R_mas (dps,1,1) i32 (dead)
//   4 WQ_w  5 WQ_b  6 WK_w  7 WK_b  8 WV_w  9 WV_b
// ---------------------------------------------------------------------------
extern "C" void kernel_launch(void* const* d_in, const int* in_sizes, int n_in,
                              void* d_out, int out_size) {
    const float* S     = (const float*)d_in[0];
    const float* R     = (const float*)d_in[1];
    const int*   S_mas = (const int*)  d_in[2];
    const float* WQ_w  = (const float*)d_in[4];
    const float* WQ_b  = (const float*)d_in[5];
    const float* WK_w  = (const float*)d_in[6];
    const float* WK_b  = (const float*)d_in[7];
    const float* WV_w  = (const float*)d_in[8];
    const float* WV_b  = (const float*)d_in[9];
    float* out = (float*)d_out;

    int dps = in_sizes[1] / 1024;          // R element count = dps*1024
    int seq = in_sizes[0] / (dps * 1024);  // S element count = dps*seq*1024

    weights_kernel<<<71, 256>>>(WQ_w, WQ_b, WK_w, WK_b, WV_w);

    constexpr int ROWS   = 64;
    constexpr int UNROLL = 4;
    int nblk = (seq + ROWS - 1) / ROWS;
    fused_kernel<ROWS, UNROLL><<<dim3(dps, nblk), 256>>>(
        S, R, S_mas, WV_b, out, seq);
}

// round 14
// speedup vs baseline: 1.3243x; 1.3243x over previous
#include <cuda_runtime.h>

// ---------------------------------------------------------------------------
// Batch-independent factorization of the collapsed reference:
//   out[b,s,h*64+e] = RV[b,h,e] * beta[b,s,h] * (S_mas[b,s] != 0)
//   beta[b,s,h] = dot(S[b,s,h*64:], W[b,h,:]) + c[b,h]
//   W[b,h,d]  = b0[d]   + sum_d' At[d',d] * r[b,h,d']     At = WQ_w^T WK_w
//   c[b,h]    = c0      + sum_d' u[d']    * r[b,h,d']     u  = WK_w^T WQ_b
//   RV[b,h,e] = WV_b[e] + sum_d  WVt[d,e] * r[b,h,d]      WVt = WV_w^T
//
// Node 1 (weights_kernel, 71 blocks, ~2-3us in-graph): At/WVt/u/b0/c0 and
//   zeroes the per-batch flags (replay-safe: edge orders it before node 2).
// Node 2 (stream kernel): blocks with y==0 (first 32 linear IDs -> wave-1
//   residents, no deadlock) compute their batch's W/RV/c from the factorized
//   weights (all loads coalesced, L2-hot), publish with threadfence + flag;
//   all other blocks spin ~2us then __ldcg the constants and stream.
// ---------------------------------------------------------------------------

__device__ float g_At [64 * 64];   // [d'][d], d fast
__device__ float g_WVt[64 * 64];   // [d][e],  e fast
__device__ float g_u  [64];
__device__ float g_b0 [64];
__device__ float g_c0;

#define MAX_DPS 64
__device__ float g_W   [MAX_DPS * 1024];
__device__ float g_RV  [MAX_DPS * 1024];
__device__ float g_C   [MAX_DPS * 16];
__device__ int   g_flag[MAX_DPS];

// ---------------------------------------------------------------------------
// weights_kernel: grid 71, block 256.
//  blocks 0..63 : At row d' = g (4-way e-split + smem reduce, coalesced).
//  blocks 64..67: WVt transpose quarter (coalesced writes).
//  block 68: u.  block 69: b0.  block 70: c0 + flag zeroing.
// ---------------------------------------------------------------------------
__global__ __launch_bounds__(256) void weights_kernel(
    const float* __restrict__ WQ_w, const float* __restrict__ WQ_b,
    const float* __restrict__ WK_w, const float* __restrict__ WK_b,
    const float* __restrict__ WV_w) {
    const int g = blockIdx.x;
    const int t = threadIdx.x;
    __shared__ float red[256];

    if (g < 64) {
        const int d    = t & 63;
        const int part = t >> 6;
        float acc = 0.f;
#pragma unroll 16
        for (int i = 0; i < 16; i++) {
            const int e = part * 16 + i;
            acc = fmaf(WQ_w[e * 64 + d], WK_w[e * 64 + g], acc);
        }
        red[t] = acc;
        __syncthreads();
        if (part == 0)
            g_At[g * 64 + d] = acc + red[d + 64] + red[d + 128] + red[d + 192];
    } else if (g < 68) {
        const int k = g - 64;
#pragma unroll
        for (int i = 0; i < 4; i++) {
            const int idx = k * 1024 + i * 256 + t;
            const int d = idx >> 6, e = idx & 63;
            g_WVt[d * 64 + e] = WV_w[e * 64 + d];
        }
    } else if (g == 68) {
        const int dp   = t & 63;
        const int part = t >> 6;
        float acc = 0.f;
#pragma unroll 16
        for (int i = 0; i < 16; i++) {
            const int e = part * 16 + i;
            acc = fmaf(WQ_b[e], WK_w[e * 64 + dp], acc);
        }
        red[t] = acc;
        __syncthreads();
        if (part == 0)
            g_u[dp] = acc + red[dp + 64] + red[dp + 128] + red[dp + 192];
    } else if (g == 69) {
        const int d    = t & 63;
        const int part = t >> 6;
        float acc = 0.f;
#pragma unroll 16
        for (int i = 0; i < 16; i++) {
            const int e = part * 16 + i;
            acc = fmaf(WQ_w[e * 64 + d], WK_b[e], acc);
        }
        red[t] = acc;
        __syncthreads();
        if (part == 0)
            g_b0[d] = acc + red[d + 64] + red[d + 128] + red[d + 192];
    } else {
        if (t < MAX_DPS) g_flag[t] = 0;    // replay-safe flag reset
        if (t == 0) {
            float a0 = 0.f, a1 = 0.f, a2 = 0.f, a3 = 0.f;
#pragma unroll 4
            for (int e = 0; e < 64; e += 4) {
                a0 = fmaf(WQ_b[e + 0], WK_b[e + 0], a0);
                a1 = fmaf(WQ_b[e + 1], WK_b[e + 1], a1);
                a2 = fmaf(WQ_b[e + 2], WK_b[e + 2], a2);
                a3 = fmaf(WQ_b[e + 3], WK_b[e + 3], a3);
            }
            g_c0 = (a0 + a1) + (a2 + a3);
        }
    }
}

// ---------------------------------------------------------------------------
// stream kernel with per-batch producer handshake.
// Producer (y==0): warp w handles heads {w, w+8} sequentially. Lane l ->
// (q = l&15 quad, half = l>>4 over d'). At/WVt reads 256B-coalesced, r via
// smem broadcast; halves combined with shfl_xor(16); coalesced stores.
// ---------------------------------------------------------------------------
template <int ROWS_PER_BLOCK, int UNROLL>
__global__ __launch_bounds__(256) void stream_kernel(
    const float* __restrict__ S,
    const float* __restrict__ R,
    const int*   __restrict__ S_mas,
    const float* __restrict__ WV_b,
    float*       __restrict__ out,
    int seq) {
    const int b = blockIdx.x;
    const int t = threadIdx.x;

    if (blockIdx.y == 0) {
        // ---- Producer: compute W/RV/c for batch b ----
        __shared__ float r_s[1024];
#pragma unroll
        for (int i = 0; i < 4; i++)
            r_s[i * 256 + t] = R[b * 1024 + i * 256 + t];
        __syncthreads();

        const int warp = t >> 5;
        const int l    = t & 31;
        const int q    = l & 15;
        const int half = l >> 4;
        const float4* At4 = reinterpret_cast<const float4*>(g_At);
        const float4* Vt4 = reinterpret_cast<const float4*>(g_WVt);

#pragma unroll
        for (int hi = 0; hi < 2; hi++) {
            const int h = warp + hi * 8;
            const float* rp = r_s + h * 64 + half * 32;
            float4 wq = {0, 0, 0, 0}, vq = {0, 0, 0, 0};
            float  c  = 0.f;
#pragma unroll 8
            for (int j = 0; j < 32; j++) {
                const int   d  = half * 32 + j;
                const float rr = rp[j];             // broadcast LDS
                const float4 a4 = At4[d * 16 + q];  // 256B coalesced, L2-hot
                wq.x = fmaf(a4.x, rr, wq.x); wq.y = fmaf(a4.y, rr, wq.y);
                wq.z = fmaf(a4.z, rr, wq.z); wq.w = fmaf(a4.w, rr, wq.w);
                const float4 v4 = Vt4[d * 16 + q];
                vq.x = fmaf(v4.x, rr, vq.x); vq.y = fmaf(v4.y, rr, vq.y);
                vq.z = fmaf(v4.z, rr, vq.z); vq.w = fmaf(v4.w, rr, vq.w);
                c = fmaf(g_u[d], rr, c);            // uniform
            }
            wq.x += __shfl_xor_sync(0xffffffffu, wq.x, 16);
            wq.y += __shfl_xor_sync(0xffffffffu, wq.y, 16);
            wq.z += __shfl_xor_sync(0xffffffffu, wq.z, 16);
            wq.w += __shfl_xor_sync(0xffffffffu, wq.w, 16);
            vq.x += __shfl_xor_sync(0xffffffffu, vq.x, 16);
            vq.y += __shfl_xor_sync(0xffffffffu, vq.y, 16);
            vq.z += __shfl_xor_sync(0xffffffffu, vq.z, 16);
            vq.w += __shfl_xor_sync(0xffffffffu, vq.w, 16);
            c    += __shfl_xor_sync(0xffffffffu, c,    16);
            if (half == 0) {
                const float4 b0q = reinterpret_cast<const float4*>(g_b0)[q];
                const float4 vbq = reinterpret_cast<const float4*>(WV_b)[q];
                reinterpret_cast<float4*>(g_W + b * 1024 + h * 64)[q] =
                    make_float4(wq.x + b0q.x, wq.y + b0q.y,
                                wq.z + b0q.z, wq.w + b0q.w);
                reinterpret_cast<float4*>(g_RV + b * 1024 + h * 64)[q] =
                    make_float4(vq.x + vbq.x, vq.y + vbq.y,
                                vq.z + vbq.z, vq.w + vbq.w);
                if (q == 0) g_C[b * 16 + h] = c + g_c0;
            }
        }
        __threadfence();
        __syncthreads();
        if (t == 0) *((volatile int*)&g_flag[b]) = 1;
    } else {
        // ---- Consumer: wait for batch b's constants ----
        if (t == 0) {
            volatile int* f = &g_flag[b];
            while (*f == 0) __nanosleep(64);
        }
        __syncthreads();
        __threadfence();
    }

    // ---- Load per-thread stream constants (L2, bypass possibly-stale L1) ----
    const int h = t >> 4;
    const float4 w4  = __ldcg(reinterpret_cast<const float4*>(g_W  + b * 1024) + t);
    const float4 rv4 = __ldcg(reinterpret_cast<const float4*>(g_RV + b * 1024) + t);
    const float  c   = __ldcg(g_C + b * 16 + h);

    // ---- Streaming pass (proven ~80us / 77% DRAM configuration) ----
    const int row0 = blockIdx.y * ROWS_PER_BLOCK;
    const float4* Sp = reinterpret_cast<const float4*>(S) + (size_t)b * seq * 256;
    float4*       Op = reinterpret_cast<float4*>(out)     + (size_t)b * seq * 256;
    const int*    mp = S_mas + (size_t)b * seq;

    const int row_end = (row0 + ROWS_PER_BLOCK < seq) ? row0 + ROWS_PER_BLOCK : seq;

    int r = row0;
    for (; r + UNROLL <= row_end; r += UNROLL) {
        float4 s[UNROLL];
        int    m[UNROLL];
#pragma unroll
        for (int u = 0; u < UNROLL; u++) {
            s[u] = Sp[(size_t)(r + u) * 256 + t];
            m[u] = mp[r + u];
        }
#pragma unroll
        for (int u = 0; u < UNROLL; u++) {
            float p = s[u].x * w4.x + s[u].y * w4.y + s[u].z * w4.z + s[u].w * w4.w;
            p += __shfl_xor_sync(0xffffffffu, p, 8, 16);
            p += __shfl_xor_sync(0xffffffffu, p, 4, 16);
            p += __shfl_xor_sync(0xffffffffu, p, 2, 16);
            p += __shfl_xor_sync(0xffffffffu, p, 1, 16);
            const float beta = (p + c) * (m[u] != 0 ? 1.0f : 0.0f);
            float4 o;
            o.x = rv4.x * beta;
            o.y = rv4.y * beta;
            o.z = rv4.z * beta;
            o.w = rv4.w * beta;
            Op[(size_t)(r + u) * 256 + t] = o;
        }
    }
    for (; r < row_end; r++) {
        float4 s = Sp[(size_t)r * 256 + t];
        int    m = mp[r];
        float p = s.x * w4.x + s.y * w4.y + s.z * w4.z + s.w * w4.w;
        p += __shfl_xor_sync(0xffffffffu, p, 8, 16);
        p += __shfl_xor_sync(0xffffffffu, p, 4, 16);
        p += __shfl_xor_sync(0xffffffffu, p, 2, 16);
        p += __shfl_xor_sync(0xffffffffu, p, 1, 16);
        const float beta = (p + c) * (m != 0 ? 1.0f : 0.0f);
        float4 o;
        o.x = rv4.x * beta;
        o.y = rv4.y * beta;
        o.z = rv4.z * beta;
        o.w = rv4.w * beta;
        Op[(size_t)r * 256 + t] = o;
    }
}

// ---------------------------------------------------------------------------
// Launch. Inputs (metadata order):
//   0 S (dps,seq,1024) f32   1 R (dps,1,1024) f32
//   2 S_mas (dps,seq,1) i32  3 R_mas (dps,1,1) i32 (dead)
//   4 WQ_w  5 WQ_b  6 WK_w  7 WK_b  8 WV_w  9 WV_b
// ---------------------------------------------------------------------------
extern "C" void kernel_launch(void* const* d_in, const int* in_sizes, int n_in,
                              void* d_out, int out_size) {
    const float* S     = (const float*)d_in[0];
    const float* R     = (const float*)d_in[1];
    const int*   S_mas = (const int*)  d_in[2];
    const float* WQ_w  = (const float*)d_in[4];
    const float* WQ_b  = (const float*)d_in[5];
    const float* WK_w  = (const float*)d_in[6];
    const float* WK_b  = (const float*)d_in[7];
    const float* WV_w  = (const float*)d_in[8];
    const float* WV_b  = (const float*)d_in[9];
    float* out = (float*)d_out;

    int dps = in_sizes[1] / 1024;          // R element count = dps*1024
    if (dps > MAX_DPS) dps = MAX_DPS;
    int seq = in_sizes[0] / (dps * 1024);  // S element count = dps*seq*1024

    weights_kernel<<<71, 256>>>(WQ_w, WQ_b, WK_w, WK_b, WV_w);

    constexpr int ROWS   = 64;
    constexpr int UNROLL = 4;
    int nblk = (seq + ROWS - 1) / ROWS;
    stream_kernel<ROWS, UNROLL><<<dim3(dps, nblk), 256>>>(
        S, R, S_mas, WV_b, out, seq);
}